// round 3
// baseline (speedup 1.0000x reference)
#include <cuda_runtime.h>
#include <cstdint>

// out[row, :] = features[rules[row], :]
// features: [N_ACTIVE=200000, C=64] fp32   (51.2 MB — fits in L2)
// rules:    [N_ROWS=524288] int32  (JAX demotes int64 -> int32 w/o x64)
// out:      [N_ROWS, 64] fp32
//
// One thread per float4 (16 float4 per row). Fully coalesced stores;
// gather reads are 2x128B lines per row, contiguous across the 16-thread group.

__global__ void __launch_bounds__(256)
bl_gather_kernel(const float4* __restrict__ feat,
                 const int* __restrict__ rules,
                 float4* __restrict__ out,
                 int total_vec4)  // n_rows * 16
{
    int idx = blockIdx.x * blockDim.x + threadIdx.x;
    if (idx >= total_vec4) return;
    int row = idx >> 4;        // which output row
    int c4  = idx & 15;        // which float4 within the row
    long long r = (long long)__ldg(&rules[row]);
    out[idx] = feat[r * 16 + c4];
}

extern "C" void kernel_launch(void* const* d_in, const int* in_sizes, int n_in,
                              void* d_out, int out_size)
{
    const float4* feat  = (const float4*)d_in[0];   // features [nActive, 64] fp32
    const int*    rules = (const int*)d_in[1];      // rules [n_rows] int32

    int n_rows     = in_sizes[1];          // 524288
    int total_vec4 = n_rows * 16;          // 8,388,608

    float4* out = (float4*)d_out;

    const int threads = 256;
    int blocks = (total_vec4 + threads - 1) / threads;
    bl_gather_kernel<<<blocks, threads>>>(feat, rules, out, total_vec4);
}

// round 4
// speedup vs baseline: 1.2800x; 1.2800x over previous
#include <cuda_runtime.h>
#include <cstdint>

// out[row, :] = features[rules[row], :]
// features: [N_ACTIVE=200000, C=64] fp32   (51.2 MB — fits in 126 MB L2)
// rules:    [N_ROWS=524288] int32
// out:      [N_ROWS, 64] fp32
//
// R3 -> R4: latency-bound fix.
//  - ILP=4 per thread (4 independent gathers in flight; ptxas front-batches the LDGs)
//  - __stcs streaming stores so the 134 MB output stream doesn't evict the
//    51 MB feature table from L2 (keeps gathers at L2 latency, not DRAM)

__global__ void __launch_bounds__(256)
bl_gather_kernel(const float4* __restrict__ feat,
                 const int* __restrict__ rules,
                 float4* __restrict__ out,
                 int total_vec4)  // n_rows * 16
{
    const int tid    = blockIdx.x * blockDim.x + threadIdx.x;
    const int stride = gridDim.x * blockDim.x;

    int  idx[4];
    long long r[4];
    float4 v[4];

    // gather phase: independent loads, batched for MLP
    #pragma unroll
    for (int i = 0; i < 4; i++) {
        idx[i] = tid + i * stride;
        int row = idx[i] >> 4;
        r[i] = (idx[i] < total_vec4) ? (long long)__ldg(&rules[row]) : 0;
    }
    #pragma unroll
    for (int i = 0; i < 4; i++) {
        int c4 = idx[i] & 15;
        if (idx[i] < total_vec4)
            v[i] = __ldg(&feat[r[i] * 16 + c4]);
    }
    // store phase: streaming hint (evict-first) to protect feature residency in L2
    #pragma unroll
    for (int i = 0; i < 4; i++) {
        if (idx[i] < total_vec4)
            __stcs(&out[idx[i]], v[i]);
    }
}

extern "C" void kernel_launch(void* const* d_in, const int* in_sizes, int n_in,
                              void* d_out, int out_size)
{
    const float4* feat  = (const float4*)d_in[0];   // features [nActive, 64] fp32
    const int*    rules = (const int*)d_in[1];      // rules [n_rows] int32

    int n_rows     = in_sizes[1];          // 524288
    int total_vec4 = n_rows * 16;          // 8,388,608

    float4* out = (float4*)d_out;

    const int threads = 256;
    const int ilp     = 4;
    int blocks = (total_vec4 + threads * ilp - 1) / (threads * ilp);  // 8192
    bl_gather_kernel<<<blocks, threads>>>(feat, rules, out, total_vec4);
}